// round 1
// baseline (speedup 1.0000x reference)
#include <cuda_runtime.h>
#include <cuda_bf16.h>
#include <cstdint>

// Problem constants
#define BATCH   16384
#define MAXF    32
#define NFEAT   768
#define FT_OUT  1024

#define FULL_MASK 0xFFFFFFFFu

// bf16 copy of ft_w, rebuilt every kernel_launch (deterministic).
// 768*1024*2 = 1.5 MB — L2-resident during the main kernel.
__device__ __nv_bfloat16 g_ftw_bf16[NFEAT * FT_OUT];

// ---------------------------------------------------------------------------
// Kernel 1: convert ft_w fp32 -> bf16 (vectorized float4 -> 2x bf162)
// 786432 elems / 4 per thread = 196608 threads
// ---------------------------------------------------------------------------
__global__ void convert_ftw_kernel(const float* __restrict__ ftw) {
    int i = blockIdx.x * blockDim.x + threadIdx.x;   // one float4 per thread
    const float4* src = reinterpret_cast<const float4*>(ftw);
    float4 v = src[i];
    __nv_bfloat162* dst = reinterpret_cast<__nv_bfloat162*>(g_ftw_bf16);
    dst[2 * i + 0] = __floats2bfloat162_rn(v.x, v.y);
    dst[2 * i + 1] = __floats2bfloat162_rn(v.z, v.w);
}

// ---------------------------------------------------------------------------
// Kernel 2: one warp per sample.
// Lane l owns columns col(c,k) = c*256 + l*8 + k   (c=0..3, k=0..7)
// Row read = 4 coalesced LDG.128 per lane (2048 B per warp per row).
// ---------------------------------------------------------------------------
__device__ __forceinline__ float bf_lo(unsigned w) { return __uint_as_float(w << 16); }
__device__ __forceinline__ float bf_hi(unsigned w) { return __uint_as_float(w & 0xFFFF0000u); }

__global__ void __launch_bounds__(256)
nnue_main_kernel(const float* __restrict__ values,
                 const int*   __restrict__ stm_idx,
                 const int*   __restrict__ nstm_idx,
                 const float* __restrict__ ft_b,
                 const float* __restrict__ out_w,
                 const float* __restrict__ out_b,
                 float*       __restrict__ out)
{
    const int gwarp = (blockIdx.x * 256 + threadIdx.x) >> 5;
    const int lane  = threadIdx.x & 31;
    if (gwarp >= BATCH) return;
    const int b = gwarp;

    // Each lane caches one feature's index (both sides) and value; broadcast via shfl.
    const int   my_is  = stm_idx [b * MAXF + lane];
    const int   my_in  = nstm_idx[b * MAXF + lane];
    const float my_val = values  [b * MAXF + lane];

    const uint4*  W   = reinterpret_cast<const uint4*>(g_ftw_bf16);  // 128 uint4 per row
    const float4* fb4 = reinterpret_cast<const float4*>(ft_b);
    const float4* ow4 = reinterpret_cast<const float4*>(out_w);

    float acc[32];
    float partial = 0.0f;

    #pragma unroll
    for (int side = 0; side < 2; ++side) {
        // init accumulators with bias
        #pragma unroll
        for (int c = 0; c < 4; ++c) {
            float4 b0 = fb4[c * 64 + lane * 2 + 0];
            float4 b1 = fb4[c * 64 + lane * 2 + 1];
            acc[c*8+0] = b0.x; acc[c*8+1] = b0.y; acc[c*8+2] = b0.z; acc[c*8+3] = b0.w;
            acc[c*8+4] = b1.x; acc[c*8+5] = b1.y; acc[c*8+6] = b1.z; acc[c*8+7] = b1.w;
        }

        const int my_idx = (side == 0) ? my_is : my_in;

        #pragma unroll 2
        for (int f = 0; f < MAXF; ++f) {
            const int   idx = __shfl_sync(FULL_MASK, my_idx, f);
            const float v   = __shfl_sync(FULL_MASK, my_val, f);
            const uint4* row = W + idx * 128;
            #pragma unroll
            for (int c = 0; c < 4; ++c) {
                uint4 d = row[c * 32 + lane];
                acc[c*8+0] = fmaf(v, bf_lo(d.x), acc[c*8+0]);
                acc[c*8+1] = fmaf(v, bf_hi(d.x), acc[c*8+1]);
                acc[c*8+2] = fmaf(v, bf_lo(d.y), acc[c*8+2]);
                acc[c*8+3] = fmaf(v, bf_hi(d.y), acc[c*8+3]);
                acc[c*8+4] = fmaf(v, bf_lo(d.z), acc[c*8+4]);
                acc[c*8+5] = fmaf(v, bf_hi(d.z), acc[c*8+5]);
                acc[c*8+6] = fmaf(v, bf_lo(d.w), acc[c*8+6]);
                acc[c*8+7] = fmaf(v, bf_hi(d.w), acc[c*8+7]);
            }
        }

        // clip [0,1] and dot with out_w slice for this side
        const int owbase = side * (FT_OUT / 4);   // in float4 units
        #pragma unroll
        for (int c = 0; c < 4; ++c) {
            float4 w0 = ow4[owbase + c * 64 + lane * 2 + 0];
            float4 w1 = ow4[owbase + c * 64 + lane * 2 + 1];
            float h;
            h = fminf(fmaxf(acc[c*8+0], 0.f), 1.f); partial = fmaf(h, w0.x, partial);
            h = fminf(fmaxf(acc[c*8+1], 0.f), 1.f); partial = fmaf(h, w0.y, partial);
            h = fminf(fmaxf(acc[c*8+2], 0.f), 1.f); partial = fmaf(h, w0.z, partial);
            h = fminf(fmaxf(acc[c*8+3], 0.f), 1.f); partial = fmaf(h, w0.w, partial);
            h = fminf(fmaxf(acc[c*8+4], 0.f), 1.f); partial = fmaf(h, w1.x, partial);
            h = fminf(fmaxf(acc[c*8+5], 0.f), 1.f); partial = fmaf(h, w1.y, partial);
            h = fminf(fmaxf(acc[c*8+6], 0.f), 1.f); partial = fmaf(h, w1.z, partial);
            h = fminf(fmaxf(acc[c*8+7], 0.f), 1.f); partial = fmaf(h, w1.w, partial);
        }
    }

    // warp reduce
    #pragma unroll
    for (int off = 16; off > 0; off >>= 1)
        partial += __shfl_xor_sync(FULL_MASK, partial, off);

    if (lane == 0) {
        float x = partial + out_b[0];
        out[b] = 1.0f / (1.0f + __expf(-x));
    }
}

// ---------------------------------------------------------------------------
// kernel_launch
// Input order (metadata): values, stm_indices, nstm_indices, ft_w, ft_b, out_w, out_b
// Output: float32 [16384]
// ---------------------------------------------------------------------------
extern "C" void kernel_launch(void* const* d_in, const int* in_sizes, int n_in,
                              void* d_out, int out_size)
{
    const float* values   = (const float*)d_in[0];
    const int*   stm_idx  = (const int*)  d_in[1];
    const int*   nstm_idx = (const int*)  d_in[2];
    const float* ft_w     = (const float*)d_in[3];
    const float* ft_b     = (const float*)d_in[4];
    const float* out_w    = (const float*)d_in[5];
    const float* out_b    = (const float*)d_in[6];
    float*       out      = (float*)d_out;

    // 1) ft_w fp32 -> bf16  (768*1024/4 = 196608 threads)
    convert_ftw_kernel<<<(NFEAT * FT_OUT / 4 + 255) / 256, 256>>>(ft_w);

    // 2) main: one warp per sample, 8 warps per CTA
    const int warps_per_cta = 256 / 32;
    const int grid = (BATCH + warps_per_cta - 1) / warps_per_cta;   // 2048
    nnue_main_kernel<<<grid, 256>>>(values, stm_idx, nstm_idx,
                                    ft_b, out_w, out_b, out);
}

// round 2
// speedup vs baseline: 1.0827x; 1.0827x over previous
#include <cuda_runtime.h>
#include <cuda_fp16.h>
#include <cstdint>

// Problem constants
#define BATCH   16384
#define MAXF    32
#define NFEAT   768
#define FT_OUT  1024

#define FULL_MASK 0xFFFFFFFFu

// fp16 copy of ft_w, rebuilt every kernel_launch (deterministic).
// 768*1024*2 = 1.5 MB — L2-resident during the main kernel.
__device__ __half g_ftw_h[NFEAT * FT_OUT];

// ---------------------------------------------------------------------------
// Kernel 1: convert ft_w fp32 -> fp16 (one float4 per thread)
// ---------------------------------------------------------------------------
__global__ void convert_ftw_kernel(const float* __restrict__ ftw) {
    int i = blockIdx.x * blockDim.x + threadIdx.x;
    float4 v = reinterpret_cast<const float4*>(ftw)[i];
    __half2* dst = reinterpret_cast<__half2*>(g_ftw_h);
    dst[2 * i + 0] = __floats2half2_rn(v.x, v.y);
    dst[2 * i + 1] = __floats2half2_rn(v.z, v.w);
}

// ---------------------------------------------------------------------------
// Kernel 2: one warp per sample, fp16 packed accumulation.
// Lane l owns columns c*256 + l*8 + k (c=0..3, k=0..7) as 4 half2 per c.
// Per feature: 4x LDG.128 + 16x HFMA2 + 2x SHFL.
// Bias added in fp32 at the epilogue (before clip) for precision.
// ---------------------------------------------------------------------------
__global__ void __launch_bounds__(256)
nnue_main_kernel(const float* __restrict__ values,
                 const int*   __restrict__ stm_idx,
                 const int*   __restrict__ nstm_idx,
                 const float* __restrict__ ft_b,
                 const float* __restrict__ out_w,
                 const float* __restrict__ out_b,
                 float*       __restrict__ out)
{
    const int gwarp = (blockIdx.x * 256 + threadIdx.x) >> 5;
    const int lane  = threadIdx.x & 31;
    if (gwarp >= BATCH) return;
    const int b = gwarp;

    // Each lane caches one feature's index (both sides) and value; broadcast via shfl.
    const int   my_is  = stm_idx [b * MAXF + lane];
    const int   my_in  = nstm_idx[b * MAXF + lane];
    const float my_val = values  [b * MAXF + lane];

    const uint4*  W   = reinterpret_cast<const uint4*>(g_ftw_h);   // 128 uint4/row
    const float4* fb4 = reinterpret_cast<const float4*>(ft_b);
    const float4* ow4 = reinterpret_cast<const float4*>(out_w);

    float partial = 0.0f;

    #pragma unroll
    for (int side = 0; side < 2; ++side) {
        const int my_idx = (side == 0) ? my_is : my_in;

        __half2 acc[16];
        #pragma unroll
        for (int i = 0; i < 16; ++i) acc[i] = __half2half2(__float2half_rn(0.0f));

        #pragma unroll 4
        for (int f = 0; f < MAXF; ++f) {
            const int   idx = __shfl_sync(FULL_MASK, my_idx, f);
            const float v   = __shfl_sync(FULL_MASK, my_val, f);
            const __half2 v2 = __float2half2_rn(v);
            const uint4* row = W + idx * 128;
            #pragma unroll
            for (int c = 0; c < 4; ++c) {
                uint4 d = row[c * 32 + lane];
                acc[c*4+0] = __hfma2(v2, *reinterpret_cast<__half2*>(&d.x), acc[c*4+0]);
                acc[c*4+1] = __hfma2(v2, *reinterpret_cast<__half2*>(&d.y), acc[c*4+1]);
                acc[c*4+2] = __hfma2(v2, *reinterpret_cast<__half2*>(&d.z), acc[c*4+2]);
                acc[c*4+3] = __hfma2(v2, *reinterpret_cast<__half2*>(&d.w), acc[c*4+3]);
            }
        }

        // epilogue: fp32 bias add, clip [0,1], dot with out_w slice
        const int owbase = side * (FT_OUT / 4);   // float4 units
        #pragma unroll
        for (int c = 0; c < 4; ++c) {
            float4 b0 = fb4[c * 64 + lane * 2 + 0];
            float4 b1 = fb4[c * 64 + lane * 2 + 1];
            float4 w0 = ow4[owbase + c * 64 + lane * 2 + 0];
            float4 w1 = ow4[owbase + c * 64 + lane * 2 + 1];
            float2 p0 = __half22float2(acc[c*4+0]);
            float2 p1 = __half22float2(acc[c*4+1]);
            float2 p2 = __half22float2(acc[c*4+2]);
            float2 p3 = __half22float2(acc[c*4+3]);
            float h;
            h = fminf(fmaxf(p0.x + b0.x, 0.f), 1.f); partial = fmaf(h, w0.x, partial);
            h = fminf(fmaxf(p0.y + b0.y, 0.f), 1.f); partial = fmaf(h, w0.y, partial);
            h = fminf(fmaxf(p1.x + b0.z, 0.f), 1.f); partial = fmaf(h, w0.z, partial);
            h = fminf(fmaxf(p1.y + b0.w, 0.f), 1.f); partial = fmaf(h, w0.w, partial);
            h = fminf(fmaxf(p2.x + b1.x, 0.f), 1.f); partial = fmaf(h, w1.x, partial);
            h = fminf(fmaxf(p2.y + b1.y, 0.f), 1.f); partial = fmaf(h, w1.y, partial);
            h = fminf(fmaxf(p3.x + b1.z, 0.f), 1.f); partial = fmaf(h, w1.z, partial);
            h = fminf(fmaxf(p3.y + b1.w, 0.f), 1.f); partial = fmaf(h, w1.w, partial);
        }
    }

    // warp reduce
    #pragma unroll
    for (int off = 16; off > 0; off >>= 1)
        partial += __shfl_xor_sync(FULL_MASK, partial, off);

    if (lane == 0) {
        float x = partial + out_b[0];
        out[b] = 1.0f / (1.0f + __expf(-x));
    }
}

// ---------------------------------------------------------------------------
// kernel_launch
// Input order (metadata): values, stm_indices, nstm_indices, ft_w, ft_b, out_w, out_b
// Output: float32 [16384]
// ---------------------------------------------------------------------------
extern "C" void kernel_launch(void* const* d_in, const int* in_sizes, int n_in,
                              void* d_out, int out_size)
{
    const float* values   = (const float*)d_in[0];
    const int*   stm_idx  = (const int*)  d_in[1];
    const int*   nstm_idx = (const int*)  d_in[2];
    const float* ft_w     = (const float*)d_in[3];
    const float* ft_b     = (const float*)d_in[4];
    const float* out_w    = (const float*)d_in[5];
    const float* out_b    = (const float*)d_in[6];
    float*       out      = (float*)d_out;

    // 1) ft_w fp32 -> fp16  (768*1024/4 = 196608 threads)
    convert_ftw_kernel<<<(NFEAT * FT_OUT / 4 + 255) / 256, 256>>>(ft_w);

    // 2) main: one warp per sample, 8 warps per CTA
    const int warps_per_cta = 256 / 32;
    const int grid = (BATCH + warps_per_cta - 1) / warps_per_cta;   // 2048
    nnue_main_kernel<<<grid, 256>>>(values, stm_idx, nstm_idx,
                                    ft_b, out_w, out_b, out);
}

// round 3
// speedup vs baseline: 1.3227x; 1.2217x over previous
#include <cuda_runtime.h>
#include <cuda_fp16.h>
#include <cstdint>

// Problem constants
#define BATCH   16384
#define MAXF    32
#define NFEAT   768
#define FT_OUT  1024

#define FULL_MASK 0xFFFFFFFFu

// fp16 copy of ft_w, rebuilt every kernel_launch (deterministic).
// 768*1024*2 = 1.5 MB — L2-resident during the main kernel.
__device__ __half g_ftw_h[NFEAT * FT_OUT];

// ---------------------------------------------------------------------------
// Kernel 1: convert ft_w fp32 -> fp16 (one float4 per thread)
// ---------------------------------------------------------------------------
__global__ void convert_ftw_kernel(const float* __restrict__ ftw) {
    int i = blockIdx.x * blockDim.x + threadIdx.x;
    float4 v = reinterpret_cast<const float4*>(ftw)[i];
    __half2* dst = reinterpret_cast<__half2*>(g_ftw_h);
    dst[2 * i + 0] = __floats2half2_rn(v.x, v.y);
    dst[2 * i + 1] = __floats2half2_rn(v.z, v.w);
}

// ---------------------------------------------------------------------------
// Kernel 2: TWO warps per sample (each owns 512 of 1024 columns),
// both sides (stm/nstm) fused in one feature loop -> 4 LDG.128 in flight.
// Per feature iteration per warp: 4x LDG.128 + 16x HFMA2 + 3x SHFL.
// Epilogue: fp32 bias+clip+dot per warp, warp-reduce, smem pair-combine.
// ---------------------------------------------------------------------------
__global__ void __launch_bounds__(256)
nnue_main_kernel(const float* __restrict__ values,
                 const int*   __restrict__ stm_idx,
                 const int*   __restrict__ nstm_idx,
                 const float* __restrict__ ft_b,
                 const float* __restrict__ out_w,
                 const float* __restrict__ out_b,
                 float*       __restrict__ out)
{
    __shared__ float s_partial[8];   // one slot per warp in CTA

    const int warpInCta = threadIdx.x >> 5;
    const int lane      = threadIdx.x & 31;
    const int gwarp     = blockIdx.x * 8 + warpInCta;
    const int b         = gwarp >> 1;        // sample
    const int h         = gwarp & 1;         // column half: 0 or 1
    // BATCH*2 warps exactly fill the grid (16384*2/8 = 4096 CTAs); no bounds check needed.

    // Each lane caches one feature's index (both sides) and value; broadcast via shfl.
    const int   my_is  = stm_idx [b * MAXF + lane];
    const int   my_in  = nstm_idx[b * MAXF + lane];
    const float my_val = values  [b * MAXF + lane];

    const uint4* W = reinterpret_cast<const uint4*>(g_ftw_h);   // 128 uint4/row
    const int h64 = h * 64;                                     // half-row offset (uint4)

    // Accumulators: 8 half2 per side (512 cols / 32 lanes / 2 per half2)
    __half2 accS[8], accN[8];
    #pragma unroll
    for (int i = 0; i < 8; ++i) {
        accS[i] = __half2half2(__float2half_rn(0.0f));
        accN[i] = accS[i];
    }

    #pragma unroll 4
    for (int f = 0; f < MAXF; ++f) {
        const int   is  = __shfl_sync(FULL_MASK, my_is,  f);
        const int   in_ = __shfl_sync(FULL_MASK, my_in,  f);
        const float v   = __shfl_sync(FULL_MASK, my_val, f);
        const __half2 v2 = __float2half2_rn(v);

        const uint4* rS = W + is  * 128 + h64;
        const uint4* rN = W + in_ * 128 + h64;
        uint4 s0 = rS[lane];
        uint4 s1 = rS[32 + lane];
        uint4 n0 = rN[lane];
        uint4 n1 = rN[32 + lane];

        accS[0] = __hfma2(v2, *reinterpret_cast<__half2*>(&s0.x), accS[0]);
        accS[1] = __hfma2(v2, *reinterpret_cast<__half2*>(&s0.y), accS[1]);
        accS[2] = __hfma2(v2, *reinterpret_cast<__half2*>(&s0.z), accS[2]);
        accS[3] = __hfma2(v2, *reinterpret_cast<__half2*>(&s0.w), accS[3]);
        accS[4] = __hfma2(v2, *reinterpret_cast<__half2*>(&s1.x), accS[4]);
        accS[5] = __hfma2(v2, *reinterpret_cast<__half2*>(&s1.y), accS[5]);
        accS[6] = __hfma2(v2, *reinterpret_cast<__half2*>(&s1.z), accS[6]);
        accS[7] = __hfma2(v2, *reinterpret_cast<__half2*>(&s1.w), accS[7]);
        accN[0] = __hfma2(v2, *reinterpret_cast<__half2*>(&n0.x), accN[0]);
        accN[1] = __hfma2(v2, *reinterpret_cast<__half2*>(&n0.y), accN[1]);
        accN[2] = __hfma2(v2, *reinterpret_cast<__half2*>(&n0.z), accN[2]);
        accN[3] = __hfma2(v2, *reinterpret_cast<__half2*>(&n0.w), accN[3]);
        accN[4] = __hfma2(v2, *reinterpret_cast<__half2*>(&n1.x), accN[4]);
        accN[5] = __hfma2(v2, *reinterpret_cast<__half2*>(&n1.y), accN[5]);
        accN[6] = __hfma2(v2, *reinterpret_cast<__half2*>(&n1.z), accN[6]);
        accN[7] = __hfma2(v2, *reinterpret_cast<__half2*>(&n1.w), accN[7]);
    }

    // ----- epilogue: fp32 bias add, clip [0,1], dot with out_w -----
    // Lane l handled uint4 indices j in {l, 32+l} of its half-row.
    // Columns for uint4 j: h*512 + j*8 + (0..7)  -> float4 index h*128 + j*2 + {0,1}
    const float4* fb4 = reinterpret_cast<const float4*>(ft_b);
    const float4* ow4 = reinterpret_cast<const float4*>(out_w);

    float partial = 0.0f;
    #pragma unroll
    for (int u = 0; u < 2; ++u) {
        const int j    = u * 32 + lane;
        const int fidx = h * 128 + j * 2;     // float4 index into 1024-col space
        float4 b0 = fb4[fidx + 0];
        float4 b1 = fb4[fidx + 1];

        #pragma unroll
        for (int side = 0; side < 2; ++side) {
            const __half2* acc = (side == 0) ? &accS[u*4] : &accN[u*4];
            const int owb = side * 256 + fidx;   // +256 float4 = +1024 cols
            float4 w0 = ow4[owb + 0];
            float4 w1 = ow4[owb + 1];
            float2 p0 = __half22float2(acc[0]);
            float2 p1 = __half22float2(acc[1]);
            float2 p2 = __half22float2(acc[2]);
            float2 p3 = __half22float2(acc[3]);
            float hh;
            hh = fminf(fmaxf(p0.x + b0.x, 0.f), 1.f); partial = fmaf(hh, w0.x, partial);
            hh = fminf(fmaxf(p0.y + b0.y, 0.f), 1.f); partial = fmaf(hh, w0.y, partial);
            hh = fminf(fmaxf(p1.x + b0.z, 0.f), 1.f); partial = fmaf(hh, w0.z, partial);
            hh = fminf(fmaxf(p1.y + b0.w, 0.f), 1.f); partial = fmaf(hh, w0.w, partial);
            hh = fminf(fmaxf(p2.x + b1.x, 0.f), 1.f); partial = fmaf(hh, w1.x, partial);
            hh = fminf(fmaxf(p2.y + b1.y, 0.f), 1.f); partial = fmaf(hh, w1.y, partial);
            hh = fminf(fmaxf(p3.x + b1.z, 0.f), 1.f); partial = fmaf(hh, w1.z, partial);
            hh = fminf(fmaxf(p3.y + b1.w, 0.f), 1.f); partial = fmaf(hh, w1.w, partial);
        }
    }

    // warp reduce
    #pragma unroll
    for (int off = 16; off > 0; off >>= 1)
        partial += __shfl_xor_sync(FULL_MASK, partial, off);

    if (lane == 0) s_partial[warpInCta] = partial;
    __syncthreads();

    // half-0 warp of each sample finalizes (warpInCta even)
    if (h == 0 && lane == 0) {
        float x = s_partial[warpInCta] + s_partial[warpInCta + 1] + out_b[0];
        out[b] = 1.0f / (1.0f + __expf(-x));
    }
}

// ---------------------------------------------------------------------------
// kernel_launch
// Input order (metadata): values, stm_indices, nstm_indices, ft_w, ft_b, out_w, out_b
// Output: float32 [16384]
// ---------------------------------------------------------------------------
extern "C" void kernel_launch(void* const* d_in, const int* in_sizes, int n_in,
                              void* d_out, int out_size)
{
    const float* values   = (const float*)d_in[0];
    const int*   stm_idx  = (const int*)  d_in[1];
    const int*   nstm_idx = (const int*)  d_in[2];
    const float* ft_w     = (const float*)d_in[3];
    const float* ft_b     = (const float*)d_in[4];
    const float* out_w    = (const float*)d_in[5];
    const float* out_b    = (const float*)d_in[6];
    float*       out      = (float*)d_out;

    // 1) ft_w fp32 -> fp16  (768*1024/4 = 196608 threads)
    convert_ftw_kernel<<<(NFEAT * FT_OUT / 4 + 255) / 256, 256>>>(ft_w);

    // 2) main: two warps per sample, 8 warps per CTA -> 4096 CTAs
    const int grid = BATCH * 2 / 8;
    nnue_main_kernel<<<grid, 256>>>(values, stm_idx, nstm_idx,
                                    ft_b, out_w, out_b, out);
}

// round 4
// speedup vs baseline: 1.3278x; 1.0039x over previous
#include <cuda_runtime.h>
#include <cuda_fp16.h>
#include <cstdint>

// Problem constants
#define BATCH   16384
#define MAXF    32
#define NFEAT   768
#define FT_OUT  1024

#define FULL_MASK 0xFFFFFFFFu

// fp16 copy of ft_w, rebuilt every kernel_launch (deterministic).
// 768*1024*2 = 1.5 MB — L2-resident during the main kernel.
__device__ __half g_ftw_h[NFEAT * FT_OUT];

// ---------------------------------------------------------------------------
// Kernel 1: convert ft_w fp32 -> fp16 (one float4 per thread)
// ---------------------------------------------------------------------------
__global__ void convert_ftw_kernel(const float* __restrict__ ftw) {
    int i = blockIdx.x * blockDim.x + threadIdx.x;
    float4 v = reinterpret_cast<const float4*>(ftw)[i];
    __half2* dst = reinterpret_cast<__half2*>(g_ftw_h);
    dst[2 * i + 0] = __floats2half2_rn(v.x, v.y);
    dst[2 * i + 1] = __floats2half2_rn(v.z, v.w);
}

// ---------------------------------------------------------------------------
// Kernel 2: TWO warps per sample (each owns 512 of 1024 columns),
// both sides (stm/nstm) fused in one feature loop -> 4 LDG.128 in flight.
// Per feature iteration per warp: 4x LDG.128 + 16x HFMA2 + 3x SHFL.
// Epilogue: fp32 bias+clip+dot per warp, warp-reduce, smem pair-combine.
// ---------------------------------------------------------------------------
__global__ void __launch_bounds__(256)
nnue_main_kernel(const float* __restrict__ values,
                 const int*   __restrict__ stm_idx,
                 const int*   __restrict__ nstm_idx,
                 const float* __restrict__ ft_b,
                 const float* __restrict__ out_w,
                 const float* __restrict__ out_b,
                 float*       __restrict__ out)
{
    __shared__ float s_partial[8];   // one slot per warp in CTA

    const int warpInCta = threadIdx.x >> 5;
    const int lane      = threadIdx.x & 31;
    const int gwarp     = blockIdx.x * 8 + warpInCta;
    const int b         = gwarp >> 1;        // sample
    const int h         = gwarp & 1;         // column half: 0 or 1
    // BATCH*2 warps exactly fill the grid (16384*2/8 = 4096 CTAs); no bounds check needed.

    // Each lane caches one feature's index (both sides) and value; broadcast via shfl.
    const int   my_is  = stm_idx [b * MAXF + lane];
    const int   my_in  = nstm_idx[b * MAXF + lane];
    const float my_val = values  [b * MAXF + lane];

    const uint4* W = reinterpret_cast<const uint4*>(g_ftw_h);   // 128 uint4/row
    const int h64 = h * 64;                                     // half-row offset (uint4)

    // Accumulators: 8 half2 per side (512 cols / 32 lanes / 2 per half2)
    __half2 accS[8], accN[8];
    #pragma unroll
    for (int i = 0; i < 8; ++i) {
        accS[i] = __half2half2(__float2half_rn(0.0f));
        accN[i] = accS[i];
    }

    #pragma unroll 4
    for (int f = 0; f < MAXF; ++f) {
        const int   is  = __shfl_sync(FULL_MASK, my_is,  f);
        const int   in_ = __shfl_sync(FULL_MASK, my_in,  f);
        const float v   = __shfl_sync(FULL_MASK, my_val, f);
        const __half2 v2 = __float2half2_rn(v);

        const uint4* rS = W + is  * 128 + h64;
        const uint4* rN = W + in_ * 128 + h64;
        uint4 s0 = rS[lane];
        uint4 s1 = rS[32 + lane];
        uint4 n0 = rN[lane];
        uint4 n1 = rN[32 + lane];

        accS[0] = __hfma2(v2, *reinterpret_cast<__half2*>(&s0.x), accS[0]);
        accS[1] = __hfma2(v2, *reinterpret_cast<__half2*>(&s0.y), accS[1]);
        accS[2] = __hfma2(v2, *reinterpret_cast<__half2*>(&s0.z), accS[2]);
        accS[3] = __hfma2(v2, *reinterpret_cast<__half2*>(&s0.w), accS[3]);
        accS[4] = __hfma2(v2, *reinterpret_cast<__half2*>(&s1.x), accS[4]);
        accS[5] = __hfma2(v2, *reinterpret_cast<__half2*>(&s1.y), accS[5]);
        accS[6] = __hfma2(v2, *reinterpret_cast<__half2*>(&s1.z), accS[6]);
        accS[7] = __hfma2(v2, *reinterpret_cast<__half2*>(&s1.w), accS[7]);
        accN[0] = __hfma2(v2, *reinterpret_cast<__half2*>(&n0.x), accN[0]);
        accN[1] = __hfma2(v2, *reinterpret_cast<__half2*>(&n0.y), accN[1]);
        accN[2] = __hfma2(v2, *reinterpret_cast<__half2*>(&n0.z), accN[2]);
        accN[3] = __hfma2(v2, *reinterpret_cast<__half2*>(&n0.w), accN[3]);
        accN[4] = __hfma2(v2, *reinterpret_cast<__half2*>(&n1.x), accN[4]);
        accN[5] = __hfma2(v2, *reinterpret_cast<__half2*>(&n1.y), accN[5]);
        accN[6] = __hfma2(v2, *reinterpret_cast<__half2*>(&n1.z), accN[6]);
        accN[7] = __hfma2(v2, *reinterpret_cast<__half2*>(&n1.w), accN[7]);
    }

    // ----- epilogue: fp32 bias add, clip [0,1], dot with out_w -----
    // Lane l handled uint4 indices j in {l, 32+l} of its half-row.
    // Columns for uint4 j: h*512 + j*8 + (0..7)  -> float4 index h*128 + j*2 + {0,1}
    const float4* fb4 = reinterpret_cast<const float4*>(ft_b);
    const float4* ow4 = reinterpret_cast<const float4*>(out_w);

    float partial = 0.0f;
    #pragma unroll
    for (int u = 0; u < 2; ++u) {
        const int j    = u * 32 + lane;
        const int fidx = h * 128 + j * 2;     // float4 index into 1024-col space
        float4 b0 = fb4[fidx + 0];
        float4 b1 = fb4[fidx + 1];

        #pragma unroll
        for (int side = 0; side < 2; ++side) {
            const __half2* acc = (side == 0) ? &accS[u*4] : &accN[u*4];
            const int owb = side * 256 + fidx;   // +256 float4 = +1024 cols
            float4 w0 = ow4[owb + 0];
            float4 w1 = ow4[owb + 1];
            float2 p0 = __half22float2(acc[0]);
            float2 p1 = __half22float2(acc[1]);
            float2 p2 = __half22float2(acc[2]);
            float2 p3 = __half22float2(acc[3]);
            float hh;
            hh = fminf(fmaxf(p0.x + b0.x, 0.f), 1.f); partial = fmaf(hh, w0.x, partial);
            hh = fminf(fmaxf(p0.y + b0.y, 0.f), 1.f); partial = fmaf(hh, w0.y, partial);
            hh = fminf(fmaxf(p1.x + b0.z, 0.f), 1.f); partial = fmaf(hh, w0.z, partial);
            hh = fminf(fmaxf(p1.y + b0.w, 0.f), 1.f); partial = fmaf(hh, w0.w, partial);
            hh = fminf(fmaxf(p2.x + b1.x, 0.f), 1.f); partial = fmaf(hh, w1.x, partial);
            hh = fminf(fmaxf(p2.y + b1.y, 0.f), 1.f); partial = fmaf(hh, w1.y, partial);
            hh = fminf(fmaxf(p3.x + b1.z, 0.f), 1.f); partial = fmaf(hh, w1.z, partial);
            hh = fminf(fmaxf(p3.y + b1.w, 0.f), 1.f); partial = fmaf(hh, w1.w, partial);
        }
    }

    // warp reduce
    #pragma unroll
    for (int off = 16; off > 0; off >>= 1)
        partial += __shfl_xor_sync(FULL_MASK, partial, off);

    if (lane == 0) s_partial[warpInCta] = partial;
    __syncthreads();

    // half-0 warp of each sample finalizes (warpInCta even)
    if (h == 0 && lane == 0) {
        float x = s_partial[warpInCta] + s_partial[warpInCta + 1] + out_b[0];
        out[b] = 1.0f / (1.0f + __expf(-x));
    }
}

// ---------------------------------------------------------------------------
// kernel_launch
// Input order (metadata): values, stm_indices, nstm_indices, ft_w, ft_b, out_w, out_b
// Output: float32 [16384]
// ---------------------------------------------------------------------------
extern "C" void kernel_launch(void* const* d_in, const int* in_sizes, int n_in,
                              void* d_out, int out_size)
{
    const float* values   = (const float*)d_in[0];
    const int*   stm_idx  = (const int*)  d_in[1];
    const int*   nstm_idx = (const int*)  d_in[2];
    const float* ft_w     = (const float*)d_in[3];
    const float* ft_b     = (const float*)d_in[4];
    const float* out_w    = (const float*)d_in[5];
    const float* out_b    = (const float*)d_in[6];
    float*       out      = (float*)d_out;

    // 1) ft_w fp32 -> fp16  (768*1024/4 = 196608 threads)
    convert_ftw_kernel<<<(NFEAT * FT_OUT / 4 + 255) / 256, 256>>>(ft_w);

    // 2) main: two warps per sample, 8 warps per CTA -> 4096 CTAs
    const int grid = BATCH * 2 / 8;
    nnue_main_kernel<<<grid, 256>>>(values, stm_idx, nstm_idx,
                                    ft_b, out_w, out_b, out);
}